// round 3
// baseline (speedup 1.0000x reference)
#include <cuda_runtime.h>
#include <cstdint>

// Wilson-Cowan, N=2^20 elements, 100 serial steps.
// R3: packed sigmoid via tanh.approx.f16x2 — ONE MUFU slot per 2 elements per
//     population (vs 1 MUFU per element in R2). y computed in f32x2 (FFMA2),
//     converted f32x2 -> f16x2 for the tanh, results converted back via
//     F2F.F32.F16 .H0/.H1. MUFU, FMA and issue floors all converge ~44K cyc.
//
// Folding (gain=1, threshold=4, dt=0.1):
//   sigmoid(x-4) = 0.5 + 0.5*tanh(0.5*(x-4))
//   yE = 6E - 2I + 0.5*(IextE - 4)        in [-4, 4]
//   yI = 6.5E - 5.5I + 0.5*(IextI - 4)    in [-7.5, 4.5]   (fp16-safe range)
//   E' = 0.99E + 0.005 + 0.005*tanh(yE)
//   I' = 0.98I + 0.01  + 0.01 *tanh(yI)
// Convex combination of state and sigma in (0,1) -> [0,1] invariant in-loop;
// exact clip applied once at the end.

typedef unsigned long long u64;

__device__ __forceinline__ u64 pack2(float lo, float hi) {
    u64 r;
    asm("mov.b64 %0, {%1, %2};" : "=l"(r) : "f"(lo), "f"(hi));
    return r;
}
__device__ __forceinline__ void unpack2(float& lo, float& hi, u64 v) {
    asm("mov.b64 {%0, %1}, %2;" : "=f"(lo), "=f"(hi) : "l"(v));
}
__device__ __forceinline__ u64 fma2(u64 a, u64 b, u64 c) {
    u64 d;
    asm("fma.rn.f32x2 %0, %1, %2, %3;" : "=l"(d) : "l"(a), "l"(b), "l"(c));
    return d;
}

// f32x2 -> tanh -> f32x2, through one packed f16x2 MUFU.TANH
__device__ __forceinline__ u64 tanh2_f16path(u64 y) {
    float lo, hi;
    unpack2(lo, hi, y);
    uint32_t h, t;
    asm("cvt.rn.f16x2.f32 %0, %1, %2;" : "=r"(h) : "f"(hi), "f"(lo)); // src0=hi half
    asm("tanh.approx.f16x2 %0, %1;" : "=r"(t) : "r"(h));
    float tlo, thi;
    asm("{ .reg .b16 l, u;            \n\t"
        "  mov.b32 {l, u}, %2;        \n\t"
        "  cvt.f32.f16 %0, l;         \n\t"
        "  cvt.f32.f16 %1, u;         }"
        : "=f"(tlo), "=f"(thi) : "r"(t));
    return pack2(tlo, thi);
}

__global__ __launch_bounds__(256)
void wilson_cowan_kernel(const float4* __restrict__ E0,
                         const float4* __restrict__ I0,
                         const float4* __restrict__ IextE,
                         const float4* __restrict__ IextI,
                         const int*    __restrict__ steps_ptr,
                         float* __restrict__ out,
                         int n,          // total elements (N)
                         int n4,         // N/4
                         int out_size)
{
    int i = blockIdx.x * blockDim.x + threadIdx.x;

    if (blockIdx.x == 0 && threadIdx.x == 0) {
        for (int k = 2 * n; k < out_size; ++k) out[k] = 0.0f;
    }
    if (i >= n4) return;

    const int steps = steps_ptr ? __ldg(steps_ptr) : 100;

    float4 e4  = E0[i];
    float4 i4  = I0[i];
    float4 xe4 = IextE[i];
    float4 xi4 = IextI[i];

    u64 E2[2] = { pack2(e4.x, e4.y), pack2(e4.z, e4.w) };
    u64 I2[2] = { pack2(i4.x, i4.y), pack2(i4.z, i4.w) };
    u64 cE2[2] = { pack2(0.5f * (xe4.x - 4.0f), 0.5f * (xe4.y - 4.0f)),
                   pack2(0.5f * (xe4.z - 4.0f), 0.5f * (xe4.w - 4.0f)) };
    u64 cI2[2] = { pack2(0.5f * (xi4.x - 4.0f), 0.5f * (xi4.y - 4.0f)),
                   pack2(0.5f * (xi4.z - 4.0f), 0.5f * (xi4.w - 4.0f)) };

    const u64 AEE = pack2( 6.0f,  6.0f);   // 0.5 * 12
    const u64 AEI = pack2(-2.0f, -2.0f);   // 0.5 * -4
    const u64 AIE = pack2( 6.5f,  6.5f);   // 0.5 * 13
    const u64 AII = pack2(-5.5f, -5.5f);   // 0.5 * -11
    const u64 ME  = pack2(0.99f, 0.99f);   // 1 - dt/tauE
    const u64 BE  = pack2(0.005f, 0.005f); // 0.5 * dt/tauE
    const u64 MI  = pack2(0.98f, 0.98f);   // 1 - dt/tauI
    const u64 BI  = pack2(0.01f, 0.01f);   // 0.5 * dt/tauI

    #pragma unroll 2
    for (int s = 0; s < steps; ++s) {
        #pragma unroll
        for (int p = 0; p < 2; ++p) {
            u64 yE = fma2(AEE, E2[p], fma2(AEI, I2[p], cE2[p]));
            u64 yI = fma2(AIE, E2[p], fma2(AII, I2[p], cI2[p]));
            u64 tE = tanh2_f16path(yE);
            u64 tI = tanh2_f16path(yI);
            E2[p] = fma2(BE, tE, fma2(ME, E2[p], BE));
            I2[p] = fma2(BI, tI, fma2(MI, I2[p], BI));
        }
    }

    float4 eo, io;
    unpack2(eo.x, eo.y, E2[0]); unpack2(eo.z, eo.w, E2[1]);
    unpack2(io.x, io.y, I2[0]); unpack2(io.z, io.w, I2[1]);
    eo.x = __saturatef(eo.x); eo.y = __saturatef(eo.y);
    eo.z = __saturatef(eo.z); eo.w = __saturatef(eo.w);
    io.x = __saturatef(io.x); io.y = __saturatef(io.y);
    io.z = __saturatef(io.z); io.w = __saturatef(io.w);

    reinterpret_cast<float4*>(out)[i]     = eo;
    reinterpret_cast<float4*>(out + n)[i] = io;
}

extern "C" void kernel_launch(void* const* d_in, const int* in_sizes, int n_in,
                              void* d_out, int out_size)
{
    const float4* E0    = (const float4*)d_in[0];
    const float4* I0    = (const float4*)d_in[1];
    const float4* IextE = (const float4*)d_in[2];
    const float4* IextI = (const float4*)d_in[3];
    const int* steps_ptr = (n_in >= 5) ? (const int*)d_in[4] : nullptr;

    int n = in_sizes[0];
    int n4 = n / 4;
    int threads = 256;
    int blocks = (n4 + threads - 1) / threads;

    wilson_cowan_kernel<<<blocks, threads>>>(E0, I0, IextE, IextI, steps_ptr,
                                             (float*)d_out, n, n4, out_size);
}